// round 16
// baseline (speedup 1.0000x reference)
#include <cuda_runtime.h>
#include <cuda_bf16.h>
#include <cuda_fp16.h>
#include <cstdint>

#define N_NODES 20000
#define HID 256
#define HEADS 8
#define DH 32
#define DEG 32
#define TOPK 16

#define MPAD 20096          // multiple of 128
#define KPAD 264            // k smem row stride (bf16), 528B

// ---------------------------------------------------------------------------
// Scratch
// ---------------------------------------------------------------------------
__device__ float g_q[N_NODES * HID];
__device__ __align__(16) __half g_vh[N_NODES * HID];              // v in fp16
__device__ __align__(16) __nv_bfloat16 g_kb[N_NODES * HID];       // k in bf16
__device__ __align__(16) __nv_bfloat16 g_ah_hi[MPAD * HID];       // h bf16 (q/k paths)
__device__ __align__(16) __half       g_ah_f16[MPAD * HID];       // h fp16 (v path)
__device__ __align__(16) __half       g_agh[MPAD * HID];          // agg fp16 (o path)
__device__ __align__(16) __nv_bfloat16 g_w_bf[2][HID * HID];      // W_q, W_k bf16
__device__ __align__(16) __half       g_w_f16[2][HID * HID];      // W_v, W_o fp16

// ---------------------------------------------------------------------------
// Splits
// ---------------------------------------------------------------------------
__global__ void split_h_kernel(const float* __restrict__ src,
                               __nv_bfloat16* __restrict__ hi,
                               __half* __restrict__ f16, int n8) {
    int g = blockIdx.x * blockDim.x + threadIdx.x;
    if (g >= n8) return;
    const float4* s = (const float4*)(src) + g * 2;
    float4 v0 = s[0], v1 = s[1];
    float vals[8] = {v0.x, v0.y, v0.z, v0.w, v1.x, v1.y, v1.z, v1.w};
    uint32_t hw[4], fw[4];
#pragma unroll
    for (int p = 0; p < 4; p++) {
        __nv_bfloat16 h0 = __float2bfloat16(vals[2 * p]);
        __nv_bfloat16 h1 = __float2bfloat16(vals[2 * p + 1]);
        hw[p] = (uint32_t)__bfloat16_as_ushort(h0) | ((uint32_t)__bfloat16_as_ushort(h1) << 16);
        __half2 hp = __floats2half2_rn(vals[2 * p], vals[2 * p + 1]);
        fw[p] = *(uint32_t*)&hp;
    }
    *(uint4*)(hi + (size_t)g * 8) = make_uint4(hw[0], hw[1], hw[2], hw[3]);
    *(uint4*)(f16 + (size_t)g * 8) = make_uint4(fw[0], fw[1], fw[2], fw[3]);
}

__global__ void split_w_kernel(const float* __restrict__ w0, const float* __restrict__ w1,
                               const float* __restrict__ w2, const float* __restrict__ w3,
                               __nv_bfloat16* __restrict__ wbf, __half* __restrict__ wf16) {
    int g = blockIdx.x * blockDim.x + threadIdx.x;
    if (g >= 4 * (HID * HID / 8)) return;
    int wi = g >> 13, idx = g & 8191;
    const float* src = (wi == 0) ? w0 : (wi == 1) ? w1 : (wi == 2) ? w2 : w3;
    const float4* s = (const float4*)(src) + idx * 2;
    float4 v0 = s[0], v1 = s[1];
    float vals[8] = {v0.x, v0.y, v0.z, v0.w, v1.x, v1.y, v1.z, v1.w};
    uint32_t ow[4];
    if (wi < 2) {
#pragma unroll
        for (int p = 0; p < 4; p++) {
            __nv_bfloat16 h0 = __float2bfloat16(vals[2 * p]);
            __nv_bfloat16 h1 = __float2bfloat16(vals[2 * p + 1]);
            ow[p] = (uint32_t)__bfloat16_as_ushort(h0) |
                    ((uint32_t)__bfloat16_as_ushort(h1) << 16);
        }
        *(uint4*)(wbf + (size_t)wi * HID * HID + (size_t)idx * 8) =
            make_uint4(ow[0], ow[1], ow[2], ow[3]);
    } else {
#pragma unroll
        for (int p = 0; p < 4; p++) {
            __half2 hp = __floats2half2_rn(vals[2 * p], vals[2 * p + 1]);
            ow[p] = *(uint32_t*)&hp;
        }
        *(uint4*)(wf16 + (size_t)(wi - 2) * HID * HID + (size_t)idx * 8) =
            make_uint4(ow[0], ow[1], ow[2], ow[3]);
    }
}

// ---------------------------------------------------------------------------
// GEMM (unchanged from R15): CTA 128x128, BK=32, 2-stage cp.async, 1-product.
// ---------------------------------------------------------------------------
#define BM 128
#define BN 128
#define BK 32
#define SA 40
#define STAGES 2
#define NITER (HID / BK)

struct Stage1 { __nv_bfloat16 Ah[BM][SA], Bh[BN][SA]; };
#define SMEM_GEMM (STAGES * (int)sizeof(Stage1))

__device__ __forceinline__ void mma16816(float* c, uint32_t a0, uint32_t a1,
                                         uint32_t a2, uint32_t a3,
                                         uint32_t b0, uint32_t b1) {
    asm volatile(
        "mma.sync.aligned.m16n8k16.row.col.f32.bf16.bf16.f32 "
        "{%0,%1,%2,%3}, {%4,%5,%6,%7}, {%8,%9}, {%0,%1,%2,%3};"
        : "+f"(c[0]), "+f"(c[1]), "+f"(c[2]), "+f"(c[3])
        : "r"(a0), "r"(a1), "r"(a2), "r"(a3), "r"(b0), "r"(b1));
}

__device__ __forceinline__ void mma16816h(float* c, uint32_t a0, uint32_t a1,
                                          uint32_t a2, uint32_t a3,
                                          uint32_t b0, uint32_t b1) {
    asm volatile(
        "mma.sync.aligned.m16n8k16.row.col.f32.f16.f16.f32 "
        "{%0,%1,%2,%3}, {%4,%5,%6,%7}, {%8,%9}, {%0,%1,%2,%3};"
        : "+f"(c[0]), "+f"(c[1]), "+f"(c[2]), "+f"(c[3])
        : "r"(a0), "r"(a1), "r"(a2), "r"(a3), "r"(b0), "r"(b1));
}

__device__ __forceinline__ void ldmx4(uint32_t* r, const void* p) {
    uint32_t a = (uint32_t)__cvta_generic_to_shared(p);
    asm volatile("ldmatrix.sync.aligned.m8n8.x4.shared.b16 {%0,%1,%2,%3}, [%4];"
                 : "=r"(r[0]), "=r"(r[1]), "=r"(r[2]), "=r"(r[3]) : "r"(a));
}

__device__ __forceinline__ void cpa16(uint32_t dst, const void* src) {
    asm volatile("cp.async.cg.shared.global [%0], [%1], 16;" :: "r"(dst), "l"(src));
}
__device__ __forceinline__ void cpa_commit() {
    asm volatile("cp.async.commit_group;" ::: "memory");
}
__device__ __forceinline__ void cpa_wait1() {
    asm volatile("cp.async.wait_group 1;" ::: "memory");
}

__device__ __forceinline__ void prefetch_stage1(
    Stage1* st, const void* pA, const void* pB, int k0, int lrow, int lseg) {
    uint32_t a;
    const uint16_t* qA = (const uint16_t*)pA;
    const uint16_t* qB = (const uint16_t*)pB;
    a = (uint32_t)__cvta_generic_to_shared(&st->Ah[lrow][lseg]);
    cpa16(a, qA + k0);  cpa16(a + 16, qA + k0 + 8);
    a = (uint32_t)__cvta_generic_to_shared(&st->Bh[lrow][lseg]);
    cpa16(a, qB + k0);  cpa16(a + 16, qB + k0 + 8);
}

template <bool FP16MMA>
__device__ __forceinline__ void mma_mainloop1(
    const void* __restrict__ Aop, const void* __restrict__ Wop,
    int m0, int n0, Stage1* stages, float (&acc)[4][4][4]) {
    const int tid = threadIdx.x;
    const int warp = tid >> 5, lane = tid & 31;
    const int wm = (warp >> 2) * 64, wn = (warp & 3) * 32;
    const int lrow = tid >> 1;
    const int lseg = (tid & 1) * 16;
    const int lg = lane & 7, sel = lane >> 3;
    const int a_row_off = (sel & 1) * 8, a_col_off = (sel >> 1) * 8;
    const int b_row_off = (sel >> 1) * 8, b_col_off = (sel & 1) * 8;

    const uint16_t* pA = (const uint16_t*)Aop + (size_t)(m0 + lrow) * HID + lseg;
    const uint16_t* pB = (const uint16_t*)Wop + (size_t)(n0 + lrow) * HID + lseg;

#pragma unroll
    for (int mt = 0; mt < 4; mt++)
#pragma unroll
        for (int nt = 0; nt < 4; nt++)
#pragma unroll
            for (int r = 0; r < 4; r++) acc[mt][nt][r] = 0.0f;

#pragma unroll
    for (int s = 0; s < STAGES; s++) {
        prefetch_stage1(&stages[s], pA, pB, s * BK, lrow, lseg);
        cpa_commit();
    }

    for (int i = 0; i < NITER; i++) {
        cpa_wait1();
        __syncthreads();
        Stage1& st = stages[i & 1];

#pragma unroll
        for (int ks = 0; ks < BK; ks += 16) {
            uint32_t bq[2][4];
#pragma unroll
            for (int p = 0; p < 2; p++) {
                int n = wn + p * 16 + lg + b_row_off;
                ldmx4(bq[p], &st.Bh[n][ks + b_col_off]);
            }
#pragma unroll
            for (int mt = 0; mt < 4; mt++) {
                int r = wm + mt * 16 + lg + a_row_off;
                uint32_t ah[4];
                ldmx4(ah, &st.Ah[r][ks + a_col_off]);
#pragma unroll
                for (int nt = 0; nt < 4; nt++) {
                    uint32_t b0 = bq[nt >> 1][(nt & 1) * 2];
                    uint32_t b1 = bq[nt >> 1][(nt & 1) * 2 + 1];
                    if (FP16MMA)
                        mma16816h(acc[mt][nt], ah[0], ah[1], ah[2], ah[3], b0, b1);
                    else
                        mma16816(acc[mt][nt], ah[0], ah[1], ah[2], ah[3], b0, b1);
                }
            }
        }

        __syncthreads();
        if (i + STAGES < NITER)
            prefetch_stage1(&stages[i & 1], pA, pB, (i + STAGES) * BK, lrow, lseg);
        cpa_commit();
    }
}

__global__ void __launch_bounds__(256, 2)
gemm_qkv(const __nv_bfloat16* __restrict__ Ahi, const __half* __restrict__ Af16,
         const __nv_bfloat16* __restrict__ wbf, const __half* __restrict__ wv16,
         const float* __restrict__ bq, const float* __restrict__ bk,
         const float* __restrict__ bv,
         float* __restrict__ qo, __nv_bfloat16* __restrict__ ko, __half* __restrict__ vo) {
    extern __shared__ char smem_raw[];
    Stage1* stages = reinterpret_cast<Stage1*>(smem_raw);
    const int which = blockIdx.x >> 1;
    const int n0 = (blockIdx.x & 1) * BN;
    const int m0 = blockIdx.y * BM;
    const float* bias = (which == 0) ? bq : (which == 1) ? bk : bv;

    float acc[4][4][4];
    if (which == 2) {
        mma_mainloop1<true>(Af16, wv16, m0, n0, stages, acc);
    } else {
        mma_mainloop1<false>(Ahi, wbf + (size_t)which * HID * HID, m0, n0, stages, acc);
    }

    const int warp = threadIdx.x >> 5, lane = threadIdx.x & 31;
    const int g = lane >> 2, t = lane & 3;
    const int wm = (warp >> 2) * 64, wn = (warp & 3) * 32;
#pragma unroll
    for (int mt = 0; mt < 4; mt++) {
#pragma unroll
        for (int nt = 0; nt < 4; nt++) {
            int col = n0 + wn + nt * 8 + 2 * t;
            float b0 = bias[col], b1 = bias[col + 1];
#pragma unroll
            for (int hh = 0; hh < 2; hh++) {
                int row = m0 + wm + mt * 16 + g + hh * 8;
                if (row < N_NODES) {
                    float v0 = acc[mt][nt][2 * hh + 0] + b0;
                    float v1 = acc[mt][nt][2 * hh + 1] + b1;
                    if (which == 0) {
                        *(float2*)&qo[(size_t)row * HID + col] = make_float2(v0, v1);
                    } else if (which == 1) {
                        uint32_t pk = (uint32_t)__bfloat16_as_ushort(__float2bfloat16(v0)) |
                                      ((uint32_t)__bfloat16_as_ushort(__float2bfloat16(v1)) << 16);
                        *(uint32_t*)&ko[(size_t)row * HID + col] = pk;
                    } else {
                        *(__half2*)&vo[(size_t)row * HID + col] =
                            __float22half2_rn(make_float2(v0, v1));
                    }
                }
            }
        }
    }
}

__global__ void __launch_bounds__(256, 2)
gemm_o(const __half* __restrict__ Agg, const __half* __restrict__ Wo16,
       const float* __restrict__ bias, float* __restrict__ C) {
    extern __shared__ char smem_raw[];
    Stage1* stages = reinterpret_cast<Stage1*>(smem_raw);
    const int n0 = blockIdx.x * BN;
    const int m0 = blockIdx.y * BM;

    float acc[4][4][4];
    mma_mainloop1<true>(Agg, Wo16, m0, n0, stages, acc);

    const int warp = threadIdx.x >> 5, lane = threadIdx.x & 31;
    const int g = lane >> 2, t = lane & 3;
    const int wm = (warp >> 2) * 64, wn = (warp & 3) * 32;
#pragma unroll
    for (int mt = 0; mt < 4; mt++) {
#pragma unroll
        for (int nt = 0; nt < 4; nt++) {
            int col = n0 + wn + nt * 8 + 2 * t;
            float b0 = bias[col], b1 = bias[col + 1];
#pragma unroll
            for (int hh = 0; hh < 2; hh++) {
                int row = m0 + wm + mt * 16 + g + hh * 8;
                if (row < N_NODES) {
                    float v0 = acc[mt][nt][2 * hh + 0] + b0;
                    float v1 = acc[mt][nt][2 * hh + 1] + b1;
                    v0 = (v0 > 0.0f) ? v0 : 0.01f * v0;
                    v1 = (v1 > 0.0f) ? v1 : 0.01f * v1;
                    *(float2*)&C[(size_t)row * HID + col] = make_float2(v0, v1);
                }
            }
        }
    }
}

// ---------------------------------------------------------------------------
// Attention: top-16 compacted k, fp16 v. L1-wavefront cuts vs R15:
//  - score q reads vectorized to float4 broadcasts (32 -> 8 LDS/warp)
//  - s_attn transposed [DEG][HEADS]: v-loop reads one warp-uniform float2
// ---------------------------------------------------------------------------
__global__ __launch_bounds__(256)
void attn_kernel(const int* __restrict__ nbr, const float* __restrict__ ew,
                 __half* __restrict__ agg) {
    const int i = blockIdx.x;
    const int tid = threadIdx.x;
    const int warp = tid >> 5;
    const int lane = tid & 31;

    __shared__ __nv_bfloat16 s_k[TOPK][KPAD];
    __shared__ __align__(16) float s_q[HID];
    __shared__ float s_w[DEG];
    __shared__ float s_attnT[DEG][HEADS];   // transposed: row = neighbor
    __shared__ float s_part[HID];
    __shared__ int   s_selnbr[TOPK];
    __shared__ int   s_nbr[DEG];
    __shared__ int   s_cidx[DEG];

    s_q[tid] = g_q[(size_t)i * HID + tid];

    if (warp == 0) {
        float w = ew[(size_t)i * DEG + lane];
        int mynb = __ldg(&nbr[(size_t)i * DEG + lane]);
        s_nbr[lane] = mynb;
        int rank = 0;
#pragma unroll
        for (int l = 0; l < DEG; l++) {
            float wl = __shfl_sync(0xffffffffu, w, l);
            rank += (wl > w) || (wl == w && l < lane);
        }
        bool sel = rank < TOPK;                 // exactly 16
        float wm = sel ? w : 0.0f;
        float s = wm;
#pragma unroll
        for (int off = 16; off; off >>= 1)
            s += __shfl_xor_sync(0xffffffffu, s, off);
        s_w[lane] = wm / (s + 1e-5f);
        uint32_t bmask = __ballot_sync(0xffffffffu, sel);
        int ci = __popc(bmask & ((1u << lane) - 1u));
        if (sel) s_selnbr[ci] = mynb;
        s_cidx[lane] = sel ? ci : -1;
    }
    __syncthreads();

    // stage k for the 16 selected rows: warp w stages rows 2w, 2w+1
#pragma unroll
    for (int jj = 0; jj < 2; jj++) {
        int r = warp * 2 + jj;
        int nb = s_selnbr[r];
        uint4 vkb = *(const uint4*)(g_kb + (size_t)nb * HID + lane * 8);
        *(uint4*)&s_k[r][lane * 8] = vkb;
    }
    __syncthreads();

    // score: warp = head, lane = original neighbor slot; q via float4 broadcasts
    const int hd = warp;
    const float4* qv = (const float4*)(s_q + hd * DH);
    const int ci = s_cidx[lane];
    float logit = 0.0f;
    if (ci >= 0) {
        const __nv_bfloat16* krow = &s_k[ci][hd * DH];
        float score = 0.0f;
#pragma unroll
        for (int c8 = 0; c8 < 4; c8++) {
            uint4 kc = *(const uint4*)(krow + c8 * 8);
            float2 p0 = __bfloat1622float2(*(__nv_bfloat162*)&kc.x);
            float2 p1 = __bfloat1622float2(*(__nv_bfloat162*)&kc.y);
            float2 p2 = __bfloat1622float2(*(__nv_bfloat162*)&kc.z);
            float2 p3 = __bfloat1622float2(*(__nv_bfloat162*)&kc.w);
            float4 qa = qv[c8 * 2];
            float4 qb = qv[c8 * 2 + 1];
            score = fmaf(p0.x, qa.x, score); score = fmaf(p0.y, qa.y, score);
            score = fmaf(p1.x, qa.z, score); score = fmaf(p1.y, qa.w, score);
            score = fmaf(p2.x, qb.x, score); score = fmaf(p2.y, qb.y, score);
            score = fmaf(p3.x, qb.z, score); score = fmaf(p3.y, qb.w, score);
        }
        logit = score * s_w[lane] * 0.17677669529663687f;  // 1/sqrt(32)
    }

    float m = logit;
#pragma unroll
    for (int off = 16; off; off >>= 1)
        m = fmaxf(m, __shfl_xor_sync(0xffffffffu, m, off));
    float e = __expf(logit - m);
    float se = e;
#pragma unroll
    for (int off = 16; off; off >>= 1)
        se += __shfl_xor_sync(0xffffffffu, se, off);
    s_attnT[lane][hd] = e / se;
    __syncthreads();

    // v aggregation (fp16): warp = (dim-group wd) x (neighbor-half); lane
    // covers dims d0, d0+1. attn pair read as one warp-uniform float2.
    const int wd = warp & 3, half = warp >> 2;
    const int d0 = wd * 64 + lane * 2;
    const bool hi_head = (lane >= 16);
    float a0 = 0.0f, a1 = 0.0f;
    const int j0 = half * 16;
#pragma unroll
    for (int j = j0; j < j0 + 16; j++) {
        float2 ap = *(const float2*)&s_attnT[j][wd * 2];   // uniform -> broadcast
        float a = hi_head ? ap.y : ap.x;
        int nb = s_nbr[j];
        float2 f = __half22float2(*(const __half2*)(g_vh + (size_t)nb * HID + d0));
        a0 = fmaf(a, f.x, a0);
        a1 = fmaf(a, f.y, a1);
    }
    if (half == 1) {
        s_part[d0] = a0;
        s_part[d0 + 1] = a1;
    }
    __syncthreads();
    if (half == 0) {
        a0 += s_part[d0];
        a1 += s_part[d0 + 1];
        *(__half2*)&agg[(size_t)i * HID + d0] = __floats2half2_rn(a0, a1);
    }
}

// ---------------------------------------------------------------------------
// Launch
// ---------------------------------------------------------------------------
extern "C" void kernel_launch(void* const* d_in, const int* in_sizes, int n_in,
                              void* d_out, int out_size) {
    const float* h   = (const float*)d_in[0];
    const int*   nbr = (const int*)d_in[1];
    const float* ew  = (const float*)d_in[2];
    const float* W_q = (const float*)d_in[3];
    const float* b_q = (const float*)d_in[4];
    const float* W_k = (const float*)d_in[5];
    const float* b_k = (const float*)d_in[6];
    const float* W_v = (const float*)d_in[7];
    const float* b_v = (const float*)d_in[8];
    const float* W_o = (const float*)d_in[9];
    const float* b_o = (const float*)d_in[10];
    float* out = (float*)d_out;

    float *q;
    __half *vh, *ah16, *agh, *wf16;
    __nv_bfloat16 *kb, *ah_hi, *wbf;
    cudaGetSymbolAddress((void**)&q, g_q);
    cudaGetSymbolAddress((void**)&vh, g_vh);
    cudaGetSymbolAddress((void**)&kb, g_kb);
    cudaGetSymbolAddress((void**)&ah_hi, g_ah_hi);
    cudaGetSymbolAddress((void**)&ah16, g_ah_f16);
    cudaGetSymbolAddress((void**)&agh, g_agh);
    cudaGetSymbolAddress((void**)&wbf, g_w_bf);
    cudaGetSymbolAddress((void**)&wf16, g_w_f16);

    cudaFuncSetAttribute(gemm_qkv, cudaFuncAttributeMaxDynamicSharedMemorySize, SMEM_GEMM);
    cudaFuncSetAttribute(gemm_o,   cudaFuncAttributeMaxDynamicSharedMemorySize, SMEM_GEMM);

    const int nA8 = N_NODES * HID / 8;

    split_h_kernel<<<(nA8 + 255) / 256, 256>>>(h, ah_hi, ah16, nA8);          // 1
    split_w_kernel<<<(4 * HID * HID / 8 + 255) / 256, 256>>>(W_q, W_k, W_v, W_o,
                                                             wbf, wf16);      // 2

    dim3 grid_qkv(6, MPAD / BM);
    gemm_qkv<<<grid_qkv, 256, SMEM_GEMM>>>(ah_hi, ah16, wbf, wf16,
                                           b_q, b_k, b_v, q, kb, vh);   // 3

    attn_kernel<<<N_NODES, 256>>>(nbr, ew, agh);                        // 4 (profiled)

    dim3 grid_o(2, MPAD / BM);
    gemm_o<<<grid_o, 256, SMEM_GEMM>>>(agh, wf16 + (size_t)HID * HID, b_o, out); // 5
}

// round 17
// speedup vs baseline: 1.0433x; 1.0433x over previous
#include <cuda_runtime.h>
#include <cuda_bf16.h>
#include <cuda_fp16.h>
#include <cstdint>

#define N_NODES 20000
#define HID 256
#define HEADS 8
#define DH 32
#define DEG 32
#define TOPK 16

#define MPAD 20096          // multiple of 128
#define KPAD 264            // k smem row stride (bf16), 528B

// ---------------------------------------------------------------------------
// Scratch
// ---------------------------------------------------------------------------
__device__ float g_q[N_NODES * HID];
__device__ __align__(16) __half g_vh[N_NODES * HID];              // v in fp16
__device__ __align__(16) __nv_bfloat16 g_kb[N_NODES * HID];       // k in bf16
__device__ __align__(16) __half g_ah[MPAD * HID];                 // h in fp16
__device__ __align__(16) __half g_agh[MPAD * HID];                // agg in fp16
__device__ __align__(16) __half g_w16[4][HID * HID];              // all weights fp16

// ---------------------------------------------------------------------------
// Splits (all fp16)
// ---------------------------------------------------------------------------
__global__ void split_h_kernel(const float* __restrict__ src,
                               __half* __restrict__ f16, int n8) {
    int g = blockIdx.x * blockDim.x + threadIdx.x;
    if (g >= n8) return;
    const float4* s = (const float4*)(src) + g * 2;
    float4 v0 = s[0], v1 = s[1];
    float vals[8] = {v0.x, v0.y, v0.z, v0.w, v1.x, v1.y, v1.z, v1.w};
    uint32_t fw[4];
#pragma unroll
    for (int p = 0; p < 4; p++) {
        __half2 hp = __floats2half2_rn(vals[2 * p], vals[2 * p + 1]);
        fw[p] = *(uint32_t*)&hp;
    }
    *(uint4*)(f16 + (size_t)g * 8) = make_uint4(fw[0], fw[1], fw[2], fw[3]);
}

__global__ void split_w_kernel(const float* __restrict__ w0, const float* __restrict__ w1,
                               const float* __restrict__ w2, const float* __restrict__ w3,
                               __half* __restrict__ wf16) {
    int g = blockIdx.x * blockDim.x + threadIdx.x;
    if (g >= 4 * (HID * HID / 8)) return;
    int wi = g >> 13, idx = g & 8191;
    const float* src = (wi == 0) ? w0 : (wi == 1) ? w1 : (wi == 2) ? w2 : w3;
    const float4* s = (const float4*)(src) + idx * 2;
    float4 v0 = s[0], v1 = s[1];
    float vals[8] = {v0.x, v0.y, v0.z, v0.w, v1.x, v1.y, v1.z, v1.w};
    uint32_t ow[4];
#pragma unroll
    for (int p = 0; p < 4; p++) {
        __half2 hp = __floats2half2_rn(vals[2 * p], vals[2 * p + 1]);
        ow[p] = *(uint32_t*)&hp;
    }
    *(uint4*)(wf16 + (size_t)wi * HID * HID + (size_t)idx * 8) =
        make_uint4(ow[0], ow[1], ow[2], ow[3]);
}

// ---------------------------------------------------------------------------
// GEMM: CTA 128x128, BK=32, 2-stage cp.async, ldmatrix, fp16 1-product.
// ---------------------------------------------------------------------------
#define BM 128
#define BN 128
#define BK 32
#define SA 40
#define STAGES 2
#define NITER (HID / BK)

struct Stage1 { __half Ah[BM][SA], Bh[BN][SA]; };
#define SMEM_GEMM (STAGES * (int)sizeof(Stage1))

__device__ __forceinline__ void mma16816h(float* c, uint32_t a0, uint32_t a1,
                                          uint32_t a2, uint32_t a3,
                                          uint32_t b0, uint32_t b1) {
    asm volatile(
        "mma.sync.aligned.m16n8k16.row.col.f32.f16.f16.f32 "
        "{%0,%1,%2,%3}, {%4,%5,%6,%7}, {%8,%9}, {%0,%1,%2,%3};"
        : "+f"(c[0]), "+f"(c[1]), "+f"(c[2]), "+f"(c[3])
        : "r"(a0), "r"(a1), "r"(a2), "r"(a3), "r"(b0), "r"(b1));
}

__device__ __forceinline__ void ldmx4(uint32_t* r, const void* p) {
    uint32_t a = (uint32_t)__cvta_generic_to_shared(p);
    asm volatile("ldmatrix.sync.aligned.m8n8.x4.shared.b16 {%0,%1,%2,%3}, [%4];"
                 : "=r"(r[0]), "=r"(r[1]), "=r"(r[2]), "=r"(r[3]) : "r"(a));
}

__device__ __forceinline__ void cpa16(uint32_t dst, const void* src) {
    asm volatile("cp.async.cg.shared.global [%0], [%1], 16;" :: "r"(dst), "l"(src));
}
__device__ __forceinline__ void cpa_commit() {
    asm volatile("cp.async.commit_group;" ::: "memory");
}
__device__ __forceinline__ void cpa_wait1() {
    asm volatile("cp.async.wait_group 1;" ::: "memory");
}

__device__ __forceinline__ void prefetch_stage1(
    Stage1* st, const __half* pA, const __half* pB, int k0, int lrow, int lseg) {
    uint32_t a;
    a = (uint32_t)__cvta_generic_to_shared(&st->Ah[lrow][lseg]);
    cpa16(a, pA + k0);  cpa16(a + 16, pA + k0 + 8);
    a = (uint32_t)__cvta_generic_to_shared(&st->Bh[lrow][lseg]);
    cpa16(a, pB + k0);  cpa16(a + 16, pB + k0 + 8);
}

__device__ __forceinline__ void mma_mainloop1(
    const __half* __restrict__ Aop, const __half* __restrict__ Wop,
    int m0, int n0, Stage1* stages, float (&acc)[4][4][4]) {
    const int tid = threadIdx.x;
    const int warp = tid >> 5, lane = tid & 31;
    const int wm = (warp >> 2) * 64, wn = (warp & 3) * 32;
    const int lrow = tid >> 1;
    const int lseg = (tid & 1) * 16;
    const int lg = lane & 7, sel = lane >> 3;
    const int a_row_off = (sel & 1) * 8, a_col_off = (sel >> 1) * 8;
    const int b_row_off = (sel >> 1) * 8, b_col_off = (sel & 1) * 8;

    const __half* pA = Aop + (size_t)(m0 + lrow) * HID + lseg;
    const __half* pB = Wop + (size_t)(n0 + lrow) * HID + lseg;

#pragma unroll
    for (int mt = 0; mt < 4; mt++)
#pragma unroll
        for (int nt = 0; nt < 4; nt++)
#pragma unroll
            for (int r = 0; r < 4; r++) acc[mt][nt][r] = 0.0f;

#pragma unroll
    for (int s = 0; s < STAGES; s++) {
        prefetch_stage1(&stages[s], pA, pB, s * BK, lrow, lseg);
        cpa_commit();
    }

    for (int i = 0; i < NITER; i++) {
        cpa_wait1();
        __syncthreads();
        Stage1& st = stages[i & 1];

#pragma unroll
        for (int ks = 0; ks < BK; ks += 16) {
            uint32_t bq[2][4];
#pragma unroll
            for (int p = 0; p < 2; p++) {
                int n = wn + p * 16 + lg + b_row_off;
                ldmx4(bq[p], &st.Bh[n][ks + b_col_off]);
            }
#pragma unroll
            for (int mt = 0; mt < 4; mt++) {
                int r = wm + mt * 16 + lg + a_row_off;
                uint32_t ah[4];
                ldmx4(ah, &st.Ah[r][ks + a_col_off]);
#pragma unroll
                for (int nt = 0; nt < 4; nt++) {
                    uint32_t b0 = bq[nt >> 1][(nt & 1) * 2];
                    uint32_t b1 = bq[nt >> 1][(nt & 1) * 2 + 1];
                    mma16816h(acc[mt][nt], ah[0], ah[1], ah[2], ah[3], b0, b1);
                }
            }
        }

        __syncthreads();
        if (i + STAGES < NITER)
            prefetch_stage1(&stages[i & 1], pA, pB, (i + STAGES) * BK, lrow, lseg);
        cpa_commit();
    }
}

__global__ void __launch_bounds__(256, 2)
gemm_qkv(const __half* __restrict__ Ah, const __half* __restrict__ w16,
         const float* __restrict__ bq, const float* __restrict__ bk,
         const float* __restrict__ bv,
         float* __restrict__ qo, __nv_bfloat16* __restrict__ ko, __half* __restrict__ vo) {
    extern __shared__ char smem_raw[];
    Stage1* stages = reinterpret_cast<Stage1*>(smem_raw);
    const int which = blockIdx.x >> 1;
    const int n0 = (blockIdx.x & 1) * BN;
    const int m0 = blockIdx.y * BM;
    const float* bias = (which == 0) ? bq : (which == 1) ? bk : bv;

    float acc[4][4][4];
    mma_mainloop1(Ah, w16 + (size_t)which * HID * HID, m0, n0, stages, acc);

    const int warp = threadIdx.x >> 5, lane = threadIdx.x & 31;
    const int g = lane >> 2, t = lane & 3;
    const int wm = (warp >> 2) * 64, wn = (warp & 3) * 32;
#pragma unroll
    for (int mt = 0; mt < 4; mt++) {
#pragma unroll
        for (int nt = 0; nt < 4; nt++) {
            int col = n0 + wn + nt * 8 + 2 * t;
            float b0 = bias[col], b1 = bias[col + 1];
#pragma unroll
            for (int hh = 0; hh < 2; hh++) {
                int row = m0 + wm + mt * 16 + g + hh * 8;
                if (row < N_NODES) {
                    float v0 = acc[mt][nt][2 * hh + 0] + b0;
                    float v1 = acc[mt][nt][2 * hh + 1] + b1;
                    if (which == 0) {
                        *(float2*)&qo[(size_t)row * HID + col] = make_float2(v0, v1);
                    } else if (which == 1) {
                        uint32_t pk = (uint32_t)__bfloat16_as_ushort(__float2bfloat16(v0)) |
                                      ((uint32_t)__bfloat16_as_ushort(__float2bfloat16(v1)) << 16);
                        *(uint32_t*)&ko[(size_t)row * HID + col] = pk;
                    } else {
                        *(__half2*)&vo[(size_t)row * HID + col] =
                            __float22half2_rn(make_float2(v0, v1));
                    }
                }
            }
        }
    }
}

__global__ void __launch_bounds__(256, 2)
gemm_o(const __half* __restrict__ Agg, const __half* __restrict__ Wo16,
       const float* __restrict__ bias, float* __restrict__ C) {
    extern __shared__ char smem_raw[];
    Stage1* stages = reinterpret_cast<Stage1*>(smem_raw);
    const int n0 = blockIdx.x * BN;
    const int m0 = blockIdx.y * BM;

    float acc[4][4][4];
    mma_mainloop1(Agg, Wo16, m0, n0, stages, acc);

    const int warp = threadIdx.x >> 5, lane = threadIdx.x & 31;
    const int g = lane >> 2, t = lane & 3;
    const int wm = (warp >> 2) * 64, wn = (warp & 3) * 32;
#pragma unroll
    for (int mt = 0; mt < 4; mt++) {
#pragma unroll
        for (int nt = 0; nt < 4; nt++) {
            int col = n0 + wn + nt * 8 + 2 * t;
            float b0 = bias[col], b1 = bias[col + 1];
#pragma unroll
            for (int hh = 0; hh < 2; hh++) {
                int row = m0 + wm + mt * 16 + g + hh * 8;
                if (row < N_NODES) {
                    float v0 = acc[mt][nt][2 * hh + 0] + b0;
                    float v1 = acc[mt][nt][2 * hh + 1] + b1;
                    v0 = (v0 > 0.0f) ? v0 : 0.01f * v0;
                    v1 = (v1 > 0.0f) ? v1 : 0.01f * v1;
                    *(float2*)&C[(size_t)row * HID + col] = make_float2(v0, v1);
                }
            }
        }
    }
}

// ---------------------------------------------------------------------------
// Attention: EXACT R15 version (frozen). top-16 compacted k, fp16 v,
// fp16 agg output.
// ---------------------------------------------------------------------------
__global__ __launch_bounds__(256)
void attn_kernel(const int* __restrict__ nbr, const float* __restrict__ ew,
                 __half* __restrict__ agg) {
    const int i = blockIdx.x;
    const int tid = threadIdx.x;
    const int warp = tid >> 5;
    const int lane = tid & 31;

    __shared__ __nv_bfloat16 s_k[TOPK][KPAD];
    __shared__ float s_q[HID];
    __shared__ float s_w[DEG];
    __shared__ float s_attn[HEADS][DEG];
    __shared__ float s_part[HID];
    __shared__ int   s_selnbr[TOPK];
    __shared__ int   s_nbr[DEG];
    __shared__ int   s_cidx[DEG];

    s_q[tid] = g_q[(size_t)i * HID + tid];

    if (warp == 0) {
        float w = ew[(size_t)i * DEG + lane];
        int mynb = __ldg(&nbr[(size_t)i * DEG + lane]);
        s_nbr[lane] = mynb;
        int rank = 0;
#pragma unroll
        for (int l = 0; l < DEG; l++) {
            float wl = __shfl_sync(0xffffffffu, w, l);
            rank += (wl > w) || (wl == w && l < lane);
        }
        bool sel = rank < TOPK;
        float wm = sel ? w : 0.0f;
        float s = wm;
#pragma unroll
        for (int off = 16; off; off >>= 1)
            s += __shfl_xor_sync(0xffffffffu, s, off);
        s_w[lane] = wm / (s + 1e-5f);
        uint32_t bmask = __ballot_sync(0xffffffffu, sel);
        int ci = __popc(bmask & ((1u << lane) - 1u));
        if (sel) s_selnbr[ci] = mynb;
        s_cidx[lane] = sel ? ci : -1;
    }
    __syncthreads();

#pragma unroll
    for (int jj = 0; jj < 2; jj++) {
        int r = warp * 2 + jj;
        int nb = s_selnbr[r];
        uint4 vkb = *(const uint4*)(g_kb + (size_t)nb * HID + lane * 8);
        *(uint4*)&s_k[r][lane * 8] = vkb;
    }
    __syncthreads();

    const int hd = warp;
    const float* qh = s_q + hd * DH;
    const int ci = s_cidx[lane];
    float logit = 0.0f;
    if (ci >= 0) {
        const __nv_bfloat16* krow = &s_k[ci][hd * DH];
        float score = 0.0f;
#pragma unroll
        for (int c8 = 0; c8 < 4; c8++) {
            uint4 kc = *(const uint4*)(krow + c8 * 8);
            float2 p0 = __bfloat1622float2(*(__nv_bfloat162*)&kc.x);
            float2 p1 = __bfloat1622float2(*(__nv_bfloat162*)&kc.y);
            float2 p2 = __bfloat1622float2(*(__nv_bfloat162*)&kc.z);
            float2 p3 = __bfloat1622float2(*(__nv_bfloat162*)&kc.w);
            const float* qb = qh + c8 * 8;
            score = fmaf(p0.x, qb[0], score); score = fmaf(p0.y, qb[1], score);
            score = fmaf(p1.x, qb[2], score); score = fmaf(p1.y, qb[3], score);
            score = fmaf(p2.x, qb[4], score); score = fmaf(p2.y, qb[5], score);
            score = fmaf(p3.x, qb[6], score); score = fmaf(p3.y, qb[7], score);
        }
        logit = score * s_w[lane] * 0.17677669529663687f;
    }

    float m = logit;
#pragma unroll
    for (int off = 16; off; off >>= 1)
        m = fmaxf(m, __shfl_xor_sync(0xffffffffu, m, off));
    float e = __expf(logit - m);
    float se = e;
#pragma unroll
    for (int off = 16; off; off >>= 1)
        se += __shfl_xor_sync(0xffffffffu, se, off);
    s_attn[hd][lane] = e / se;
    __syncthreads();

    const int wd = warp & 3, half = warp >> 2;
    const int d0 = wd * 64 + lane * 2;
    const int head2 = d0 >> 5;
    float a0 = 0.0f, a1 = 0.0f;
    const int j0 = half * 16;
#pragma unroll
    for (int j = j0; j < j0 + 16; j++) {
        float a = s_attn[head2][j];
        int nb = s_nbr[j];
        float2 f = __half22float2(*(const __half2*)(g_vh + (size_t)nb * HID + d0));
        a0 = fmaf(a, f.x, a0);
        a1 = fmaf(a, f.y, a1);
    }
    if (half == 1) {
        s_part[d0] = a0;
        s_part[d0 + 1] = a1;
    }
    __syncthreads();
    if (half == 0) {
        a0 += s_part[d0];
        a1 += s_part[d0 + 1];
        *(__half2*)&agg[(size_t)i * HID + d0] = __floats2half2_rn(a0, a1);
    }
}

// ---------------------------------------------------------------------------
// Launch
// ---------------------------------------------------------------------------
extern "C" void kernel_launch(void* const* d_in, const int* in_sizes, int n_in,
                              void* d_out, int out_size) {
    const float* h   = (const float*)d_in[0];
    const int*   nbr = (const int*)d_in[1];
    const float* ew  = (const float*)d_in[2];
    const float* W_q = (const float*)d_in[3];
    const float* b_q = (const float*)d_in[4];
    const float* W_k = (const float*)d_in[5];
    const float* b_k = (const float*)d_in[6];
    const float* W_v = (const float*)d_in[7];
    const float* b_v = (const float*)d_in[8];
    const float* W_o = (const float*)d_in[9];
    const float* b_o = (const float*)d_in[10];
    float* out = (float*)d_out;

    float *q;
    __half *vh, *ah16, *agh, *w16;
    __nv_bfloat16 *kb;
    cudaGetSymbolAddress((void**)&q, g_q);
    cudaGetSymbolAddress((void**)&vh, g_vh);
    cudaGetSymbolAddress((void**)&kb, g_kb);
    cudaGetSymbolAddress((void**)&ah16, g_ah);
    cudaGetSymbolAddress((void**)&agh, g_agh);
    cudaGetSymbolAddress((void**)&w16, g_w16);

    cudaFuncSetAttribute(gemm_qkv, cudaFuncAttributeMaxDynamicSharedMemorySize, SMEM_GEMM);
    cudaFuncSetAttribute(gemm_o,   cudaFuncAttributeMaxDynamicSharedMemorySize, SMEM_GEMM);

    const int nA8 = N_NODES * HID / 8;

    split_h_kernel<<<(nA8 + 255) / 256, 256>>>(h, ah16, nA8);                 // 1
    split_w_kernel<<<(4 * HID * HID / 8 + 255) / 256, 256>>>(W_q, W_k, W_v, W_o, w16); // 2

    dim3 grid_qkv(6, MPAD / BM);
    gemm_qkv<<<grid_qkv, 256, SMEM_GEMM>>>(ah16, w16, b_q, b_k, b_v, q, kb, vh); // 3

    attn_kernel<<<N_NODES, 256>>>(nbr, ew, agh);                              // 4 (profiled)

    dim3 grid_o(2, MPAD / BM);
    gemm_o<<<grid_o, 256, SMEM_GEMM>>>(agh, w16 + 3 * (size_t)HID * HID, b_o, out); // 5
}